// round 16
// baseline (speedup 1.0000x reference)
#include <cuda_runtime.h>
#include <math.h>

#define NBOX  4096
#define STUP  128               // setup threads; scan runs on warp 0 only
#define SLOTS 2304
#define GC    8                 // 8x8 spatial grid, 128px cells
#define NCELL (GC * GC)
#define MAXB  64
#define FULL  0xFFFFFFFFu

typedef unsigned long long u64;
typedef unsigned u32;

__device__ u64 g_emit[2][NBOX];
__device__ int g_mcnt[2];

struct ScanSmem {
    float4 sbx[SLOTS];          // box per slot (cell-grouped)       36 KB
    u64    skey[SLOTS];        // (scorebits<<32)|~orig ; 0 = dead  18 KB
    int    acc[MAXB];          // accepted slots, epoch order
    int    cstart[NCELL + 1];
    int    ccnt[NCELL];
    int    ccur[NCELL];
};

extern __shared__ char smem_raw[];

__device__ __forceinline__ u64 warpmax64(u64 v) {
    u32 h  = (u32)(v >> 32);
    u32 mh = __reduce_max_sync(FULL, h);
    u32 l  = (h == mh) ? (u32)v : 0u;
    u32 ml = __reduce_max_sync(FULL, l);
    return ((u64)mh << 32) | ml;
}

// Decay register-cached candidate q (box bq, area aq) by accepted box ab/aa.
__device__ __forceinline__ void cand_decay(u64& q, const float4& bq, float aq,
                                           const float4& ab, float aa) {
    if (q != 0ULL) {
        float w = fminf(ab.z, bq.z) - fmaxf(ab.x, bq.x);
        float h = fminf(ab.w, bq.w) - fmaxf(ab.y, bq.y);
        if (w > 0.0f && h > 0.0f) {
            float inter = w * h;
            float iou = inter / ((aa + aq) - inter + 1e-8f);
            float d   = expf(-(iou * iou) * 2.0f);      // sigma=0.5
            float nv  = __uint_as_float((u32)(q >> 32)) * d;
            q = (nv >= 0.001f)
                ? (((u64)__float_as_uint(nv) << 32) | (u32)q) : 0ULL;
        }
    }
}

__global__ __launch_bounds__(STUP, 1)
void scan_kernel(const float* __restrict__ g_boxes,
                 const float* __restrict__ g_scores,
                 const int*   __restrict__ g_labels)
{
    ScanSmem* sm = reinterpret_cast<ScanSmem*>(smem_raw);
    const int cls = blockIdx.x;
    const int tid = threadIdx.x;
    const int lid = tid & 31;

    // ============ setup (128 threads): bin own class by cell ============
    for (int c = tid; c < NCELL; c += STUP) { sm->ccnt[c] = 0; sm->ccur[c] = 0; }
    __syncthreads();
    for (int j = tid; j < NBOX; j += STUP) {
        if (g_labels[j] == cls) {
            float4 b = reinterpret_cast<const float4*>(g_boxes)[j];
            int cell = ((((int)b.y) >> 7) << 3) | (((int)b.x) >> 7);
            atomicAdd(&sm->ccnt[cell], 1);
        }
    }
    __syncthreads();
    if (tid == 0) {
        int run = 0;
        for (int c = 0; c < NCELL; c++) { sm->cstart[c] = run; run += sm->ccnt[c]; }
        sm->cstart[NCELL] = run;
    }
    __syncthreads();
    for (int j = tid; j < NBOX; j += STUP) {
        if (g_labels[j] == cls) {
            float4 b = reinterpret_cast<const float4*>(g_boxes)[j];
            int cell = ((((int)b.y) >> 7) << 3) | (((int)b.x) >> 7);
            int pos = sm->cstart[cell] + atomicAdd(&sm->ccur[cell], 1);
            sm->sbx[pos]  = b;
            sm->skey[pos] = ((u64)__float_as_uint(g_scores[j]) << 32) | (u32)~j;
        }
    }
    __syncthreads();
    if (tid >= 32) return;       // single-warp scan; no block barriers after

    const int Ng  = sm->cstart[NCELL];
    const int ept = (Ng + 31) >> 5;
    const int lo  = lid * ept;
    const int hi  = min(lo + ept, Ng);

    // lane-private candidate queue: top-3 keys+slots+cached boxes, 4th key
    u64 q0 = 0, q1 = 0, q2 = 0, k3 = 0;
    int s0 = 0, s1 = 0, s2 = 0;
    float4 b0, b1, b2;
    float  a0 = 0, a1 = 0, a2 = 0;
    bool changed = true;
    int emitted = 0;

    while (true) {
        // ---- recompute lane top-4 (only changed lanes pay) ----
        if (changed) {
            q0 = q1 = q2 = k3 = 0; s0 = s1 = s2 = 0;
            for (int p = lo; p < hi; p++) {
                u64 k = sm->skey[p];
                if (k > q0)      { k3 = q2; q2 = q1; s2 = s1; q1 = q0; s1 = s0; q0 = k; s0 = p; }
                else if (k > q1) { k3 = q2; q2 = q1; s2 = s1; q1 = k;  s1 = p; }
                else if (k > q2) { k3 = q2; q2 = k;  s2 = p; }
                else if (k > k3) { k3 = k; }
            }
            if (q0) { b0 = sm->sbx[s0]; a0 = (b0.z - b0.x) * (b0.w - b0.y); }
            if (q1) { b1 = sm->sbx[s1]; a1 = (b1.z - b1.x) * (b1.w - b1.y); }
            if (q2) { b2 = sm->sbx[s2]; a2 = (b2.z - b2.x) * (b2.w - b2.y); }
            changed = false;
        }

        // ---- epoch bound: every unqueued current key <= bound ----
        u64 bound = warpmax64(k3);

        // ---- batch accept loop: no barriers, no publish ----
        int bcount = 0;
        while (true) {
            u64 lm = q0 > q1 ? q0 : q1; if (q2 > lm) lm = q2;
            u64 win = warpmax64(lm);
            if (win == 0ULL) break;
            if (bcount > 0 && win < bound) break;
            if (bcount >= MAXB) break;

            // winner lane pops its matching entry; slot broadcast via redux
            u32 myslot = 0u;
            if (lm == win) {
                if (q0 == win)      { myslot = (u32)(s0 + 1); q0 = 0; }
                else if (q1 == win) { myslot = (u32)(s1 + 1); q1 = 0; }
                else                { myslot = (u32)(s2 + 1); q2 = 0; }
                changed = true;
            }
            int wslot = (int)__reduce_max_sync(FULL, myslot) - 1;
            if (lid == 0) { g_emit[cls][emitted] = win; sm->acc[bcount] = wslot; }
            emitted++; bcount++;

            float4 ab = sm->sbx[wslot];                 // broadcast LDS
            float  aa = (ab.z - ab.x) * (ab.w - ab.y);
            cand_decay(q0, b0, a0, ab, aa);
            cand_decay(q1, b1, a1, ab, aa);
            cand_decay(q2, b2, a2, ab, aa);
        }

        if (bcount == 0) break;                         // class done (exact)
        __syncwarp();

        // ---- epoch-end: apply accepted boxes (in order) to smem scores,
        //      each lane only within its range ∩ 3x3 cell neighborhood ----
        for (int b = 0; b < bcount; b++) {
            int wslot = sm->acc[b];
            float4 ab = sm->sbx[wslot];
            float  aa = (ab.z - ab.x) * (ab.w - ab.y);
            int cx = ((int)ab.x) >> 7, cy = ((int)ab.y) >> 7;
            int cxlo = max(cx - 1, 0), cxhi = min(cx + 1, GC - 1);
            int cylo = max(cy - 1, 0), cyhi = min(cy + 1, GC - 1);
            for (int ry = cylo; ry <= cyhi; ry++) {
                int plo = max(sm->cstart[ry * GC + cxlo], lo);
                int phi = min(sm->cstart[ry * GC + cxhi + 1], hi);
                for (int p = plo; p < phi; p++) {
                    u64 k = sm->skey[p];
                    if (k == 0ULL) continue;
                    if (p == wslot) {                    // emitted: deactivate
                        sm->skey[p] = 0ULL; changed = true; continue;
                    }
                    float4 bb = sm->sbx[p];
                    float w  = fminf(ab.z, bb.z) - fmaxf(ab.x, bb.x);
                    float hh = fminf(ab.w, bb.w) - fmaxf(ab.y, bb.y);
                    if (w > 0.0f && hh > 0.0f) {
                        float a2v   = (bb.z - bb.x) * (bb.w - bb.y);
                        float inter = w * hh;
                        float iou   = inter / ((aa + a2v) - inter + 1e-8f);
                        float d     = expf(-(iou * iou) * 2.0f);
                        float nv    = __uint_as_float((u32)(k >> 32)) * d;
                        sm->skey[p] = (nv >= 0.001f)
                            ? (((u64)__float_as_uint(nv) << 32) | (u32)k) : 0ULL;
                        changed = true;
                    }
                }
            }
        }
        __syncwarp();
    }

    if (lid == 0) g_mcnt[cls] = emitted;
}

// ---------------- merge kernel (1 CTA, smem-staged keys) ----------------
#define MNT 1024
__global__ __launch_bounds__(MNT, 1)
void merge_kernel(const float* __restrict__ g_boxes,
                  float* __restrict__ g_out)
{
    __shared__ u64 sA[NBOX];
    const int tid = threadIdx.x;
    const int mA = g_mcnt[0];
    const int mB = g_mcnt[1];

    for (int i = tid; i < mA; i += MNT) sA[i]      = g_emit[0][i];
    for (int i = tid; i < mB; i += MNT) sA[mA + i] = g_emit[1][i];
    __syncthreads();

    float* outBoxes  = g_out;             // [N,4]
    float* outScores = g_out + 4 * NBOX;  // [N]
    float* outLabels = g_out + 5 * NBOX;  // [N] float; -1 padding

    for (int i = tid; i < mA; i += MNT) {
        u64 key = sA[i];
        int lo = 0, hi = mB;
        while (lo < hi) { int mid = (lo + hi) >> 1;
                          if (sA[mA + mid] > key) lo = mid + 1; else hi = mid; }
        int r = i + lo;
        int o = (int)~(u32)key;
        reinterpret_cast<float4*>(outBoxes)[r] =
            reinterpret_cast<const float4*>(g_boxes)[o];
        outScores[r] = __uint_as_float((u32)(key >> 32));
        outLabels[r] = 0.0f;
    }
    for (int i = tid; i < mB; i += MNT) {
        u64 key = sA[mA + i];
        int lo = 0, hi = mA;
        while (lo < hi) { int mid = (lo + hi) >> 1;
                          if (sA[mid] > key) lo = mid + 1; else hi = mid; }
        int r = i + lo;
        int o = (int)~(u32)key;
        reinterpret_cast<float4*>(outBoxes)[r] =
            reinterpret_cast<const float4*>(g_boxes)[o];
        outScores[r] = __uint_as_float((u32)(key >> 32));
        outLabels[r] = 1.0f;
    }
    for (int r = mA + mB + tid; r < NBOX; r += MNT) {
        reinterpret_cast<float4*>(outBoxes)[r] = make_float4(0.f, 0.f, 0.f, 0.f);
        outScores[r] = 0.0f;
        outLabels[r] = -1.0f;
    }
}

extern "C" void kernel_launch(void* const* d_in, const int* in_sizes, int n_in,
                              void* d_out, int out_size)
{
    const float* boxes  = (const float*)d_in[0];
    const float* scores = (const float*)d_in[1];
    const int*   labels = (const int*)d_in[2];
    float*       out    = (float*)d_out;

    size_t smem = sizeof(ScanSmem);
    cudaFuncSetAttribute(scan_kernel,
                         cudaFuncAttributeMaxDynamicSharedMemorySize, (int)smem);
    scan_kernel<<<2, STUP, smem>>>(boxes, scores, labels);
    merge_kernel<<<1, MNT>>>(boxes, out);
}

// round 17
// speedup vs baseline: 18.4555x; 18.4555x over previous
#include <cuda_runtime.h>
#include <math.h>

#define NBOX 4096
#define NT   256                 // threads per class CTA (8 warps)
#define NW   (NT / 32)
#define EPT  9                   // contiguous slots per thread: 2304 capacity
#define RBEG (EPT * NT)
#define GC   8                   // 8x8 spatial grid, 128px cells
#define NCELL (GC * GC)
#define NCAND (NW * 4)
#define MAXB 32
#define FULL 0xFFFFFFFFu

typedef unsigned long long u64;
typedef unsigned u32;

__device__ u64 g_emit[2][NBOX];
__device__ int g_mcnt[2];

struct ScanSmem {
    float4 sbox[NBOX];           // orig-indexed boxes                64 KB
    float  cscore[NBOX];         // cell-sorted slot scores           16 KB
    int    corig[NBOX];          // slot -> orig index                16 KB
    u64    cand[NCAND];
    u32    cflag[NCAND];         // 1 = publication was lane's THIRD
    int    cstart[NCELL + 1];
    int    ccnt[NCELL];
    int    ccur[NCELL];
    int    cnt;
};

extern __shared__ char smem_raw[];

__device__ __forceinline__ u64 packkey(float s, int orig) {
    return ((u64)__float_as_uint(fmaxf(s, 0.0f)) << 32) | (u32)~orig;
}

__global__ __launch_bounds__(NT, 1)
void scan_kernel(const float* __restrict__ g_boxes,
                 const float* __restrict__ g_scores,
                 const int*   __restrict__ g_labels)
{
    ScanSmem* sm = reinterpret_cast<ScanSmem*>(smem_raw);
    const int cls = blockIdx.x;
    const int tid = threadIdx.x;
    const int wid = tid >> 5;
    const int lid = tid & 31;

    // ---- setup: load boxes; bin own class by 8x8 cell (spatial sort) ----
    for (int c = tid; c < NCELL; c += NT) { sm->ccnt[c] = 0; sm->ccur[c] = 0; }
    __syncthreads();
    for (int j = tid; j < NBOX; j += NT) {
        float4 b = reinterpret_cast<const float4*>(g_boxes)[j];
        sm->sbox[j] = b;
        if (g_labels[j] == cls) {
            int cell = ((((int)b.y) >> 7) << 3) | (((int)b.x) >> 7);
            atomicAdd(&sm->ccnt[cell], 1);
        }
    }
    __syncthreads();
    if (tid == 0) {
        int run = 0;
        for (int c = 0; c < NCELL; c++) { sm->cstart[c] = run; run += sm->ccnt[c]; }
        sm->cstart[NCELL] = run;
        sm->cnt = run;
    }
    __syncthreads();
    for (int j = tid; j < NBOX; j += NT) {
        if (g_labels[j] == cls) {
            float4 b = sm->sbox[j];
            int cell = ((((int)b.y) >> 7) << 3) | (((int)b.x) >> 7);
            int pos = sm->cstart[cell] + atomicAdd(&sm->ccur[cell], 1);
            sm->cscore[pos] = g_scores[j];
            sm->corig[pos]  = j;
        }
    }
    __syncthreads();
    const int Ng = sm->cnt;

    // ---- contiguous (spatial) ownership: slots [tid*EPT, tid*EPT+EPT) ----
    float sc[EPT], bx[EPT], by[EPT], bz[EPT], bw[EPT], ar[EPT];
    int   org[EPT];
    float aax1 = 1e30f, aay1 = 1e30f, aax2 = -1e30f, aay2 = -1e30f;
#pragma unroll
    for (int k = 0; k < EPT; k++) {
        int s = tid * EPT + k;
        if (s < Ng) {
            int o = sm->corig[s];
            float4 b = sm->sbox[o];
            bx[k] = b.x; by[k] = b.y; bz[k] = b.z; bw[k] = b.w;
            ar[k] = (b.z - b.x) * (b.w - b.y);
            sc[k] = sm->cscore[s];
            org[k] = o;
            aax1 = fminf(aax1, b.x); aay1 = fminf(aay1, b.y);
            aax2 = fmaxf(aax2, b.z); aay2 = fmaxf(aay2, b.w);
        } else { sc[k] = -INFINITY; org[k] = -1; }
    }

    bool changed = true;
    u64  la0 = 0, la1 = 0, la2 = 0;   // cached local top-3 packed keys
    int  emitted = 0;

    while (true) {
        // ---- recompute local top-3 if owned set changed ----
        if (changed) {
            u64 a = 0, b = 0, c = 0;
#pragma unroll
            for (int k = 0; k < EPT; k++) {
                u64 v = (sc[k] == -INFINITY) ? 0ULL : packkey(sc[k], org[k]);
                if (v > a)      { c = b; b = a; a = v; }
                else if (v > b) { c = b; b = v; }
                else if (v > c) { c = v; }
            }
            for (int s = RBEG + tid; s < Ng; s += NT) {       // overflow (rare)
                float sv = sm->cscore[s];
                u64 v = (sv == -INFINITY) ? 0ULL : packkey(sv, sm->corig[s]);
                if (v > a)      { c = b; b = a; a = v; }
                else if (v > b) { c = b; b = v; }
                else if (v > c) { c = v; }
            }
            la0 = a; la1 = b; la2 = c;
            changed = false;
        }

        // ---- publish per-warp top-4 (lanes offer their top-3) ----
        {
            int p = 0;
#pragma unroll
            for (int r = 0; r < 4; r++) {
                u64 contrib = (p == 0) ? la0 : ((p == 1) ? la1 :
                              ((p == 2) ? la2 : 0ULL));
                u32 hi = (u32)(contrib >> 32);
                u32 wm = __reduce_max_sync(FULL, hi);
                u32 lo = (hi == wm) ? (u32)contrib : 0u;
                u32 wl = __reduce_max_sync(FULL, lo);
                u64 win = ((u64)wm << 32) | wl;
                if (win != 0ULL && contrib == win) {
                    sm->cand[wid * 4 + r]  = win;
                    sm->cflag[wid * 4 + r] = (p == 2) ? 1u : 0u;
                    p++;
                }
                if (win == 0ULL && lid == 0) sm->cand[wid * 4 + r] = 0ULL;
            }
        }
        __syncthreads();                 // the ONLY barrier in the loop

        // ---- bound: >= every non-candidate's current key ----
        u64 ck = sm->cand[lid];
        u32 third = sm->cflag[lid];
        u64 bref = (ck != 0ULL && (third || (lid & 3) == 3)) ? ck : 0ULL;
        u32 bh = (u32)(bref >> 32);
        u32 bm = __reduce_max_sync(FULL, bh);
        u32 bl = (bh == bm) ? (u32)bref : 0u;
        u32 bml = __reduce_max_sync(FULL, bl);
        u64 bound = ((u64)bm << 32) | bml;

        int corig = -1; float csc = 0.0f, ca = 0.0f;
        float4 cb = make_float4(0.f, 0.f, 0.f, 0.f);
        if (ck != 0ULL) {
            corig = (int)~(u32)ck;
            csc = __uint_as_float((u32)(ck >> 32));
            cb = sm->sbox[corig];
            ca = (cb.z - cb.x) * (cb.w - cb.y);
        }
        u64 cur = ck;

        // ---- batch accept loop with INLINE owned decay (no 2nd barrier).
        //      win is block-uniform: all warps hold identical candidates
        //      and apply identical decay -> identical sequences. ----
        int bcount = 0;
        while (true) {
            u32 hi = (u32)(cur >> 32);
            u32 wm = __reduce_max_sync(FULL, hi);
            if (wm == 0u) break;
            u32 lo = (hi == wm) ? (u32)cur : 0u;
            u32 wl = __reduce_max_sync(FULL, lo);
            u64 win = ((u64)wm << 32) | wl;
            if (bcount > 0 && win < bound) break;
            int so = (int)~wl;
            if (tid == 0) g_emit[cls][emitted] = win;
            emitted++; bcount++;

            float4 ab = sm->sbox[so];                   // broadcast LDS
            float  aa = (ab.z - ab.x) * (ab.w - ab.y);

            // candidate-copy decay (keeps accept sequence exact)
            if (cur != 0ULL) {
                if (corig == so) cur = 0ULL;
                else {
                    float w = fminf(ab.z, cb.z) - fmaxf(ab.x, cb.x);
                    float h = fminf(ab.w, cb.w) - fmaxf(ab.y, cb.y);
                    if (w > 0.0f && h > 0.0f) {
                        float inter = w * h;
                        float iou = inter / ((aa + ca) - inter + 1e-8f);
                        float d   = expf(-(iou * iou) * 2.0f);
                        float nv  = csc * d;
                        if (nv >= 0.001f) {
                            csc = nv;
                            cur = ((u64)__float_as_uint(csc) << 32) | (u32)~corig;
                        } else cur = 0ULL;
                    }
                }
            }

            // owned-register decay, AABB-gated (emission order preserved)
            bool hit = (ab.x < aax2) && (ab.z > aax1) &&
                       (ab.y < aay2) && (ab.w > aay1);
            if (hit) {
#pragma unroll
                for (int k = 0; k < EPT; k++) {
                    float v = sc[k];
                    if (v != -INFINITY) {
                        if (org[k] == so) { sc[k] = -INFINITY; changed = true; }
                        else {
                            float w = fminf(ab.z, bz[k]) - fmaxf(ab.x, bx[k]);
                            float h = fminf(ab.w, bw[k]) - fmaxf(ab.y, by[k]);
                            if (w > 0.0f && h > 0.0f) {
                                float inter = w * h;
                                float iou = inter / ((aa + ar[k]) - inter + 1e-8f);
                                float d   = expf(-(iou * iou) * 2.0f);
                                float nv  = v * d;
                                sc[k] = (nv >= 0.001f) ? nv : -INFINITY;
                                changed = true;
                            }
                        }
                    }
                }
            }
            // overflow region (rare; Ng <= RBEG in practice)
            for (int s = RBEG + tid; s < Ng; s += NT) {
                float v = sm->cscore[s];
                if (v != -INFINITY) {
                    int o = sm->corig[s];
                    if (o == so) { sm->cscore[s] = -INFINITY; changed = true; }
                    else {
                        float4 b2 = sm->sbox[o];
                        float w = fminf(ab.z, b2.z) - fmaxf(ab.x, b2.x);
                        float h = fminf(ab.w, b2.w) - fmaxf(ab.y, b2.y);
                        if (w > 0.0f && h > 0.0f) {
                            float a2 = (b2.z - b2.x) * (b2.w - b2.y);
                            float inter = w * h;
                            float iou = inter / ((aa + a2) - inter + 1e-8f);
                            float d   = expf(-(iou * iou) * 2.0f);
                            float nv  = v * d;
                            sm->cscore[s] = (nv >= 0.001f) ? nv : -INFINITY;
                            changed = true;
                        }
                    }
                }
            }
            if (bcount >= MAXB) break;
        }

        if (bcount == 0) break;                         // class done
    }

    if (tid == 0) g_mcnt[cls] = emitted;
}

// ---------------- merge kernel (1 CTA, smem-staged keys) ----------------
#define MNT 1024
__global__ __launch_bounds__(MNT, 1)
void merge_kernel(const float* __restrict__ g_boxes,
                  float* __restrict__ g_out)
{
    __shared__ u64 sA[NBOX];
    const int tid = threadIdx.x;
    const int mA = g_mcnt[0];
    const int mB = g_mcnt[1];

    for (int i = tid; i < mA; i += MNT) sA[i]      = g_emit[0][i];
    for (int i = tid; i < mB; i += MNT) sA[mA + i] = g_emit[1][i];
    __syncthreads();

    float* outBoxes  = g_out;
    float* outScores = g_out + 4 * NBOX;
    float* outLabels = g_out + 5 * NBOX;

    for (int i = tid; i < mA; i += MNT) {
        u64 key = sA[i];
        int lo = 0, hi = mB;
        while (lo < hi) { int mid = (lo + hi) >> 1;
                          if (sA[mA + mid] > key) lo = mid + 1; else hi = mid; }
        int r = i + lo;
        int o = (int)~(u32)key;
        reinterpret_cast<float4*>(outBoxes)[r] =
            reinterpret_cast<const float4*>(g_boxes)[o];
        outScores[r] = __uint_as_float((u32)(key >> 32));
        outLabels[r] = 0.0f;
    }
    for (int i = tid; i < mB; i += MNT) {
        u64 key = sA[mA + i];
        int lo = 0, hi = mA;
        while (lo < hi) { int mid = (lo + hi) >> 1;
                          if (sA[mid] > key) lo = mid + 1; else hi = mid; }
        int r = i + lo;
        int o = (int)~(u32)key;
        reinterpret_cast<float4*>(outBoxes)[r] =
            reinterpret_cast<const float4*>(g_boxes)[o];
        outScores[r] = __uint_as_float((u32)(key >> 32));
        outLabels[r] = 1.0f;
    }
    for (int r = mA + mB + tid; r < NBOX; r += MNT) {
        reinterpret_cast<float4*>(outBoxes)[r] = make_float4(0.f, 0.f, 0.f, 0.f);
        outScores[r] = 0.0f;
        outLabels[r] = -1.0f;
    }
}

extern "C" void kernel_launch(void* const* d_in, const int* in_sizes, int n_in,
                              void* d_out, int out_size)
{
    const float* boxes  = (const float*)d_in[0];
    const float* scores = (const float*)d_in[1];
    const int*   labels = (const int*)d_in[2];
    float*       out    = (float*)d_out;

    size_t smem = sizeof(ScanSmem);
    cudaFuncSetAttribute(scan_kernel,
                         cudaFuncAttributeMaxDynamicSharedMemorySize, (int)smem);
    scan_kernel<<<2, NT, smem>>>(boxes, scores, labels);
    merge_kernel<<<1, MNT>>>(boxes, out);
}